// round 15
// baseline (speedup 1.0000x reference)
#include <cuda_runtime.h>
#include <math.h>
#include <float.h>
#include <stdint.h>

#define BB   8
#define NN   512
#define CC   256
#define HE   32
#define F0   64
#define OUTD 2
#define MTOT (BB*NN)   // 4096
#define PSTAGE 4

// ---------------- scratch ----------------
__device__ float g_xab[MTOT*64];
__device__ float g_Ap[BB*NN*NN];
__device__ float g_S0[MTOT];
__device__ float g_S1[MTOT];
__device__ float g_P0[MTOT*F0];
__device__ float g_P1[MTOT*F0];
__device__ float g_Y0[MTOT*F0];
__device__ float g_Y1[MTOT*F0];
__device__ int   g_gmax[BB*F0];

// ---------------- helpers ----------------
__device__ __forceinline__ float tf32_rn(float x) {
    uint32_t u;
    asm("cvt.rna.tf32.f32 %0, %1;" : "=r"(u) : "f"(x));
    return __uint_as_float(u);
}
__device__ __forceinline__ void mma_tf32(float c[4], const uint32_t a[4], const uint32_t b[2]) {
    asm volatile(
        "mma.sync.aligned.m16n8k8.row.col.f32.tf32.tf32.f32 "
        "{%0,%1,%2,%3}, {%4,%5,%6,%7}, {%8,%9}, {%0,%1,%2,%3};\n"
        : "+f"(c[0]), "+f"(c[1]), "+f"(c[2]), "+f"(c[3])
        : "r"(a[0]), "r"(a[1]), "r"(a[2]), "r"(a[3]), "r"(b[0]), "r"(b[1]));
}
__device__ __forceinline__ float dinv(float s) { return rsqrtf(s + 1.0f + 1e-5f); }
__device__ __forceinline__ void barg(int id) {
    asm volatile("bar.sync %0, 128;" :: "r"(id) : "memory");
}
__device__ __forceinline__ float relu_(float x) { return fmaxf(x, 0.f); }
__device__ __forceinline__ uint32_t s2u(const void* p) {
    return (uint32_t)__cvta_generic_to_shared(p);
}
__device__ __forceinline__ void cpa16(uint32_t dst, const void* src) {
    asm volatile("cp.async.cg.shared.global [%0], [%1], 16;" :: "r"(dst), "l"(src) : "memory");
}
__device__ __forceinline__ void cpa_commit() {
    asm volatile("cp.async.commit_group;" ::: "memory");
}
__device__ __forceinline__ void cpa_wait2() {
    asm volatile("cp.async.wait_group 2;" ::: "memory");
}

// ---------------- colsum of A (direct) + zero S1/gmax ----------------
__global__ __launch_bounds__(256) void k_colsumA(const float* __restrict__ A) {
    int b = blockIdx.y, c0 = blockIdx.x*16;
    int tc = threadIdx.x & 15, tr = threadIdx.x >> 4;
    float s = 0.f;
    const float* base = A + (size_t)b*NN*NN;
#pragma unroll 8
    for (int r = tr; r < NN; r += 16)
        s += base[(size_t)r*NN + c0 + tc];
    __shared__ float sm[16][17];
    sm[tr][tc] = s;
    __syncthreads();
    if (tr == 0) {
        float tot = 0.f;
#pragma unroll
        for (int q = 0; q < 16; ++q) tot += sm[q][tc];
        g_S0[b*NN + c0 + tc] = tot;
    }
    int blk = blockIdx.y*32 + blockIdx.x;
    if (threadIdx.x < 16) g_S1[blk*16 + threadIdx.x] = 0.f;
    if (blk < 32 && threadIdx.x < 16) g_gmax[blk*16 + threadIdx.x] = 0;
}

// ---------------- g_xab = x @ [wa | wb], eb1 folded ----------------
__global__ __launch_bounds__(256) void k_xab(const float* __restrict__ x,
                                             const float* __restrict__ ew1,
                                             const float* __restrict__ eb1) {
    int m0 = blockIdx.x*64;
    __shared__ float As[16][64];
    __shared__ float Bs[16][64];
    int t = threadIdx.x;
    int tx = t & 15, ty = t >> 4;
    float acc[4][4] = {};

    for (int k0 = 0; k0 < CC; k0 += 16) {
        {
            int row = t >> 2, kq = (t & 3)*4;
            float4 v = *(const float4*)&x[(size_t)(m0+row)*CC + k0 + kq];
            As[kq+0][row] = v.x; As[kq+1][row] = v.y; As[kq+2][row] = v.z; As[kq+3][row] = v.w;
        }
        {
            int kk = t >> 4, nq = (t & 15)*4;
            const float* src = (nq < 32) ? &ew1[(size_t)(k0+kk)*HE + nq]
                                         : &ew1[(size_t)(k0+kk+CC)*HE + nq - 32];
            *(float4*)&Bs[kk][nq] = *(const float4*)src;
        }
        __syncthreads();
#pragma unroll
        for (int k = 0; k < 16; ++k) {
            float4 a = *(const float4*)&As[k][ty*4];
            float4 bv = *(const float4*)&Bs[k][tx*4];
            float av[4] = {a.x, a.y, a.z, a.w};
            float bb[4] = {bv.x, bv.y, bv.z, bv.w};
#pragma unroll
            for (int u = 0; u < 4; ++u)
#pragma unroll
                for (int v2 = 0; v2 < 4; ++v2)
                    acc[u][v2] = fmaf(av[u], bb[v2], acc[u][v2]);
        }
        __syncthreads();
    }
#pragma unroll
    for (int u = 0; u < 4; ++u) {
        int row = m0 + ty*4 + u;
        float o[4];
#pragma unroll
        for (int v2 = 0; v2 < 4; ++v2) {
            int col = tx*4 + v2;
            o[v2] = acc[u][v2] + (col >= 32 ? eb1[col-32] : 0.f);
        }
        *(float4*)&g_xab[(size_t)row*64 + tx*4] = make_float4(o[0], o[1], o[2], o[3]);
    }
}

// ---------------- fused edge-MLP + symmetrize + exp + mask + colsum(S1) ----------------
__global__ __launch_bounds__(256) void k_edge_sym(const float* __restrict__ mask,
                                                  const float* __restrict__ ew2,
                                                  const float* __restrict__ eb2) {
    int idx = blockIdx.x, bi = 0;
    while (idx >= 16 - bi) { idx -= 16 - bi; ++bi; }
    int bj = bi + idx;
    int b = blockIdx.y;
    int i0 = bi*32, j0 = bj*32;
    bool diag = (bi == bj);
    __shared__ float sin_[32][68];
    __shared__ float sjf[64][33];
    __shared__ __align__(16) float wv[32];
    __shared__ float mi_s[32], mj_s[32];
    __shared__ float red[8][32];
    int tx = threadIdx.x, ty = threadIdx.y;
    int t = ty*32 + tx;
    for (int q = t; q < 512; q += 256) {
        int node = q >> 4, c = (q & 15)*4;
        float4 vi = *(const float4*)&g_xab[(size_t)(b*NN + i0 + node)*64 + c];
        *(float4*)&sin_[node][c] = vi;
        float4 vj = *(const float4*)&g_xab[(size_t)(b*NN + j0 + node)*64 + c];
        sjf[c+0][node] = vj.x; sjf[c+1][node] = vj.y; sjf[c+2][node] = vj.z; sjf[c+3][node] = vj.w;
    }
    if (t < 32) { wv[t] = ew2[t]; mi_s[t] = mask[b*NN + i0 + t]; mj_s[t] = mask[b*NN + j0 + t]; }
    __syncthreads();

    float e2v = eb2[0];
    float acc1[4], acc2[4];
#pragma unroll
    for (int r = 0; r < 4; ++r) { acc1[r] = e2v; acc2[r] = e2v; }

#pragma unroll
    for (int kc = 0; kc < 32; kc += 4) {
        float4 wq = *(const float4*)&wv[kc];
        float aj0 = sjf[kc+0][tx], aj1 = sjf[kc+1][tx];
        float aj2 = sjf[kc+2][tx], aj3 = sjf[kc+3][tx];
        float bj0 = sjf[32+kc+0][tx], bj1 = sjf[32+kc+1][tx];
        float bj2 = sjf[32+kc+2][tx], bj3 = sjf[32+kc+3][tx];
#pragma unroll
        for (int r = 0; r < 4; ++r) {
            int il = ty + r*8;
            float4 ai = *(const float4*)&sin_[il][kc];
            float4 bi = *(const float4*)&sin_[il][32+kc];
            acc1[r] = fmaf(relu_(ai.x + bj0), wq.x, acc1[r]);
            acc1[r] = fmaf(relu_(ai.y + bj1), wq.y, acc1[r]);
            acc1[r] = fmaf(relu_(ai.z + bj2), wq.z, acc1[r]);
            acc1[r] = fmaf(relu_(ai.w + bj3), wq.w, acc1[r]);
            acc2[r] = fmaf(relu_(aj0 + bi.x), wq.x, acc2[r]);
            acc2[r] = fmaf(relu_(aj1 + bi.y), wq.y, acc2[r]);
            acc2[r] = fmaf(relu_(aj2 + bi.z), wq.z, acc2[r]);
            acc2[r] = fmaf(relu_(aj3 + bi.w), wq.w, acc2[r]);
        }
    }

    float colacc = 0.f;
#pragma unroll
    for (int r = 0; r < 4; ++r) {
        int il = ty + r*8, jl = tx;
        int gi = i0 + il, gj = j0 + jl;
        float v = 0.f;
        if (gi != gj && mi_s[il] > 0.f && mj_s[jl] > 0.f)
            v = __expf(0.5f*(acc1[r] + acc2[r]));
        g_Ap[((size_t)b*NN + gi)*NN + gj] = v;
        colacc += v;
        if (!diag) {
            g_Ap[((size_t)b*NN + gj)*NN + gi] = v;
            float rs = v;
#pragma unroll
            for (int off = 16; off; off >>= 1) rs += __shfl_xor_sync(0xffffffffu, rs, off);
            if (tx == 0) atomicAdd(&g_S1[b*NN + gi], rs);
        }
    }
    red[ty][tx] = colacc;
    __syncthreads();
    if (ty == 0) {
        float tot = 0.f;
#pragma unroll
        for (int q = 0; q < 8; ++q) tot += red[q][tx];
        atomicAdd(&g_S1[b*NN + j0 + tx], tot);
    }
}

// ---------------- projection v6: TF32 MMA, cp.async 4-stage, M=32 x N=128, BK=16 ----------------
// 8 warps (2m x 4n); s = wn>>1. A-side 2xTF32 compensation at fragment time.
__global__ __launch_bounds__(256) void k_proj_mma(const float* __restrict__ xin,
                                                  const float* __restrict__ biasPrev,
                                                  const float* __restrict__ W,
                                                  const float* __restrict__ mask,
                                                  int mode, int K) {
    int m0 = blockIdx.x*32;
    __shared__ float Araw[PSTAGE][32][20];    // [stage][m][k], stride 20 (bank-clean)
    __shared__ float Braw[PSTAGE][16][136];   // [stage][k][n], stride 136
    int t = threadIdx.x;
    int lane = t & 31, warp = t >> 5;
    int wm = warp >> 2, wn = warp & 3;
    int g = lane >> 2, tig = lane & 3;
    int s = wn >> 1;
    const float* Sp = s ? g_S1 : g_S0;
    float* P = s ? g_P1 : g_P0;

    float acc[4][4] = {};   // nt x 4

    // A loader (t<128): arow = t>>2 (0..31), akq = (t&3)*4
    int arow = t >> 2, akq = (t & 3)*4;
    bool aload = (t < 128);
    // B loader (all): 2 float4/thread
    int q0 = t*2, q1 = t*2 + 1;
    int bk0 = q0 >> 5, bn0 = (q0 & 31)*4;
    int bk1 = q1 >> 5, bn1 = (q1 & 31)*4;
    const float* WB0 = W + (size_t)(bn0 >= 64 ? K*F0 : 0);
    const float* WB1 = W + (size_t)(bn1 >= 64 ? K*F0 : 0);
    int bc0 = bn0 & 63, bc1 = bn1 & 63;

    int NCH = K >> 4;

    auto issue = [&](int c) {
        if (c < NCH) {
            int st = c & (PSTAGE-1);
            int k0 = c << 4;
            if (aload) {
                if (mode == 0) {
                    cpa16(s2u(&Araw[st][arow][akq]), &xin[(size_t)(m0+arow)*CC + k0 + akq]);
                } else {
                    int grow = m0 + arow;
                    float4 y0 = *(const float4*)&g_Y0[(size_t)grow*F0 + k0 + akq];
                    float4 y1 = *(const float4*)&g_Y1[(size_t)grow*F0 + k0 + akq];
                    float4 bp = *(const float4*)&biasPrev[k0 + akq];
                    float mk = mask[grow];
                    float4 v;
                    v.x = relu_((y0.x + y1.x + bp.x)*mk);
                    v.y = relu_((y0.y + y1.y + bp.y)*mk);
                    v.z = relu_((y0.z + y1.z + bp.z)*mk);
                    v.w = relu_((y0.w + y1.w + bp.w)*mk);
                    *(float4*)&Araw[st][arow][akq] = v;
                }
            }
            cpa16(s2u(&Braw[st][bk0][bn0]), &WB0[(size_t)(k0+bk0)*F0 + bc0]);
            cpa16(s2u(&Braw[st][bk1][bn1]), &WB1[(size_t)(k0+bk1)*F0 + bc1]);
        }
        cpa_commit();   // empty group when c >= NCH (keeps wait_group bookkeeping exact)
    };

    issue(0); issue(1); issue(2);

    for (int c = 0; c < NCH; ++c) {
        cpa_wait2();
        __syncthreads();
        int st = c & (PSTAGE-1);
        int m = wm*16 + g;
#pragma unroll
        for (int kb = 0; kb < 16; kb += 8) {
            float r0 = Araw[st][m  ][kb+tig];
            float r1 = Araw[st][m+8][kb+tig];
            float r2 = Araw[st][m  ][kb+tig+4];
            float r3 = Araw[st][m+8][kb+tig+4];
            uint32_t ah[4], al[4], bh[4][2];
            float h0 = tf32_rn(r0), h1 = tf32_rn(r1), h2 = tf32_rn(r2), h3 = tf32_rn(r3);
            ah[0] = __float_as_uint(h0); al[0] = __float_as_uint(tf32_rn(r0 - h0));
            ah[1] = __float_as_uint(h1); al[1] = __float_as_uint(tf32_rn(r1 - h1));
            ah[2] = __float_as_uint(h2); al[2] = __float_as_uint(tf32_rn(r2 - h2));
            ah[3] = __float_as_uint(h3); al[3] = __float_as_uint(tf32_rn(r3 - h3));
#pragma unroll
            for (int nt = 0; nt < 4; ++nt) {
                int n = wn*32 + nt*8 + g;
                bh[nt][0] = __float_as_uint(tf32_rn(Braw[st][kb+tig  ][n]));
                bh[nt][1] = __float_as_uint(tf32_rn(Braw[st][kb+tig+4][n]));
            }
#pragma unroll
            for (int nt = 0; nt < 4; ++nt) {
                mma_tf32(acc[nt], al, bh[nt]);   // A-residual
                mma_tf32(acc[nt], ah, bh[nt]);   // main
            }
        }
        __syncthreads();
        issue(c + 3);
    }

    int r0 = m0 + wm*16 + g;
    float d0 = dinv(Sp[r0]), d8 = dinv(Sp[r0+8]);
#pragma unroll
    for (int nt = 0; nt < 4; ++nt) {
        int cc = (wn*32 + nt*8 + 2*tig) & 63;
        *(float2*)&P[(size_t)r0*F0 + cc] =
            make_float2(tf32_rn(acc[nt][0]*d0), tf32_rn(acc[nt][1]*d0));
        *(float2*)&P[(size_t)(r0+8)*F0 + cc] =
            make_float2(tf32_rn(acc[nt][2]*d8), tf32_rn(acc[nt][3]*d8));
    }
}

// ---------------- Y_s = D_s*(A_s @ P_s + P_s) — TF32 MMA, split-K ----------------
__global__ __launch_bounds__(256) void k_LL_mma(const float* __restrict__ Ain) {
    int m0 = blockIdx.x*64;
    int z = blockIdx.y, b = z >> 1, s = z & 1;
    const float* Am = (s ? g_Ap : Ain) + (size_t)b*NN*NN;
    const float* P  = (s ? g_P1 : g_P0) + (size_t)b*NN*F0;
    float* Y        = (s ? g_Y1 : g_Y0) + (size_t)b*NN*F0;
    const float* Sp = (s ? g_S1 : g_S0) + b*NN;

    __shared__ float As[2][16][72];
    __shared__ float Bs[2][16][72];
    __shared__ float red[4096];
    int t = threadIdx.x;
    int lane = t & 31, warp = t >> 5;
    int gq = warp >> 2, wg = warp & 3;
    int g = lane >> 2, tig = lane & 3;
    int wm = wg >> 1, wn = wg & 1;
    int tg = t & 127;
    int barid = gq + 1;

    float acc[2][4][4] = {};

    int qa0 = tg*2, qa1 = tg*2 + 1;
    int ar0 = qa0 >> 2, akq0 = (qa0 & 3)*4;
    int ar1 = qa1 >> 2, akq1 = (qa1 & 3)*4;
    int bk0 = qa0 >> 4, bnq0 = (qa0 & 15)*4;
    int bk1 = qa1 >> 4, bnq1 = (qa1 & 15)*4;

    int kstart = gq*16;
    float4 aR0 = *(const float4*)&Am[(size_t)(m0+ar0)*NN + kstart + akq0];
    float4 aR1 = *(const float4*)&Am[(size_t)(m0+ar1)*NN + kstart + akq1];
    float4 bR0 = *(const float4*)&P[(size_t)(kstart+bk0)*F0 + bnq0];
    float4 bR1 = *(const float4*)&P[(size_t)(kstart+bk1)*F0 + bnq1];

    for (int k0 = kstart; k0 < NN; k0 += 32) {
        As[gq][akq0+0][ar0] = tf32_rn(aR0.x); As[gq][akq0+1][ar0] = tf32_rn(aR0.y);
        As[gq][akq0+2][ar0] = tf32_rn(aR0.z); As[gq][akq0+3][ar0] = tf32_rn(aR0.w);
        As[gq][akq1+0][ar1] = tf32_rn(aR1.x); As[gq][akq1+1][ar1] = tf32_rn(aR1.y);
        As[gq][akq1+2][ar1] = tf32_rn(aR1.z); As[gq][akq1+3][ar1] = tf32_rn(aR1.w);
        Bs[gq][bk0][bnq0+0] = bR0.x; Bs[gq][bk0][bnq0+1] = bR0.y;
        Bs[gq][bk0][bnq0+2] = bR0.z; Bs[gq][bk0][bnq0+3] = bR0.w;
        Bs[gq][bk1][bnq1+0] = bR1.x; Bs[gq][bk1][bnq1+1] = bR1.y;
        Bs[gq][bk1][bnq1+2] = bR1.z; Bs[gq][bk1][bnq1+3] = bR1.w;
        barg(barid);

        if (k0 + 32 < NN) {
            int kn = k0 + 32;
            aR0 = *(const float4*)&Am[(size_t)(m0+ar0)*NN + kn + akq0];
            aR1 = *(const float4*)&Am[(size_t)(m0+ar1)*NN + kn + akq1];
            bR0 = *(const float4*)&P[(size_t)(kn+bk0)*F0 + bnq0];
            bR1 = *(const float4*)&P[(size_t)(kn+bk1)*F0 + bnq1];
        }

#pragma unroll
        for (int kb = 0; kb < 16; kb += 8) {
            uint32_t af[2][4], bf[4][2];
#pragma unroll
            for (int mt = 0; mt < 2; ++mt) {
                int m = wm*32 + mt*16 + g;
                af[mt][0] = __float_as_uint(As[gq][kb+tig  ][m]);
                af[mt][1] = __float_as_uint(As[gq][kb+tig  ][m+8]);
                af[mt][2] = __float_as_uint(As[gq][kb+tig+4][m]);
                af[mt][3] = __float_as_uint(As[gq][kb+tig+4][m+8]);
            }
#pragma unroll
            for (int nt = 0; nt < 4; ++nt) {
                int n = wn*32 + nt*8 + g;
                bf[nt][0] = __float_as_uint(Bs[gq][kb+tig  ][n]);
                bf[nt][1] = __float_as_uint(Bs[gq][kb+tig+4][n]);
            }
#pragma unroll
            for (int mt = 0; mt < 2; ++mt)
#pragma unroll
                for (int nt = 0; nt < 4; ++nt)
                    mma_tf32(acc[mt][nt], af[mt], bf[nt]);
        }
        barg(barid);
    }

    if (gq == 1) {
#pragma unroll
        for (int mt = 0; mt < 2; ++mt)
#pragma unroll
            for (int nt = 0; nt < 4; ++nt)
                *(float4*)&red[(((wg*2+mt)*4+nt)*32 + lane)*4] =
                    make_float4(acc[mt][nt][0], acc[mt][nt][1], acc[mt][nt][2], acc[mt][nt][3]);
    }
    __syncthreads();
    if (gq == 0) {
#pragma unroll
        for (int mt = 0; mt < 2; ++mt)
#pragma unroll
            for (int nt = 0; nt < 4; ++nt) {
                float4 rv = *(const float4*)&red[(((wg*2+mt)*4+nt)*32 + lane)*4];
                float c0 = acc[mt][nt][0] + rv.x;
                float c1 = acc[mt][nt][1] + rv.y;
                float c2 = acc[mt][nt][2] + rv.z;
                float c3 = acc[mt][nt][3] + rv.w;
                int r0 = m0 + wm*32 + mt*16 + g;
                int cc = wn*32 + nt*8 + 2*tig;
                float d0 = dinv(Sp[r0]), d8 = dinv(Sp[r0+8]);
                float2 p0 = *(const float2*)&P[(size_t)r0*F0 + cc];
                float2 p8 = *(const float2*)&P[(size_t)(r0+8)*F0 + cc];
                *(float2*)&Y[(size_t)r0*F0 + cc]     = make_float2(d0*(c0 + p0.x), d0*(c1 + p0.y));
                *(float2*)&Y[(size_t)(r0+8)*F0 + cc] = make_float2(d8*(c2 + p8.x), d8*(c3 + p8.y));
            }
    }
}

// ---------------- final stage 1 ----------------
__global__ __launch_bounds__(256) void k_finalmax(const float* __restrict__ gb2,
                                                  const float* __restrict__ mask) {
    int b = blockIdx.y, r0 = blockIdx.x*32;
    int f = threadIdx.x & 63;
    int ty = threadIdx.x >> 6;
    float bf = gb2[f];
    float m = 0.f;
#pragma unroll
    for (int r = 0; r < 8; ++r) {
        int row = b*NN + r0 + ty + r*4;
        float h = (g_Y0[(size_t)row*F0 + f] + g_Y1[(size_t)row*F0 + f] + bf)*mask[row];
        m = fmaxf(m, h);
    }
    __shared__ float red[4][64];
    red[ty][f] = m;
    __syncthreads();
    if (ty == 0) {
        float mm = fmaxf(fmaxf(red[0][f], red[1][f]), fmaxf(red[2][f], red[3][f]));
        atomicMax(&g_gmax[b*F0 + f], __float_as_int(mm));
    }
}

// ---------------- final stage 2 ----------------
__global__ __launch_bounds__(512) void k_fc(const float* __restrict__ fcw,
                                            const float* __restrict__ fcb,
                                            float* __restrict__ out) {
    __shared__ float gs[BB][F0];
    int t = threadIdx.x;
    gs[t >> 6][t & 63] = __int_as_float(g_gmax[t]);
    __syncthreads();
    if (t < BB*OUTD) {
        int b = t >> 1, o = t & 1;
        float acc = fcb[o];
#pragma unroll
        for (int q = 0; q < F0; ++q) acc = fmaf(gs[b][q], fcw[q*OUTD + o], acc);
        out[b*OUTD + o] = acc;
    }
}

// ---------------- launch ----------------
extern "C" void kernel_launch(void* const* d_in, const int* in_sizes, int n_in,
                              void* d_out, int out_size) {
    const float* x    = (const float*)d_in[0];
    const float* A    = (const float*)d_in[1];
    const float* mask = (const float*)d_in[2];
    const float* ew1  = (const float*)d_in[3];
    const float* eb1  = (const float*)d_in[4];
    const float* ew2  = (const float*)d_in[5];
    const float* eb2  = (const float*)d_in[6];
    const float* gw0  = (const float*)d_in[7];
    const float* gb0  = (const float*)d_in[8];
    const float* gw1  = (const float*)d_in[9];
    const float* gb1  = (const float*)d_in[10];
    const float* gw2  = (const float*)d_in[11];
    const float* gb2  = (const float*)d_in[12];
    const float* fcw  = (const float*)d_in[13];
    const float* fcb  = (const float*)d_in[14];
    float* out = (float*)d_out;

    k_colsumA<<<dim3(32, BB), 256>>>(A);                        // 1 (zeros S1, gmax)
    k_xab<<<MTOT/64, 256>>>(x, ew1, eb1);                       // 2
    k_edge_sym<<<dim3(136, BB), dim3(32, 8)>>>(mask, ew2, eb2); // 3
    k_proj_mma<<<MTOT/32, 256>>>(x, nullptr, gw0, mask, 0, CC); // 4 (profiled slot)
    k_LL_mma<<<dim3(NN/64, BB*2), 256>>>(A);                    // 5
    k_proj_mma<<<MTOT/32, 256>>>(nullptr, gb0, gw1, mask, 1, F0); // 6
    k_LL_mma<<<dim3(NN/64, BB*2), 256>>>(A);                    // 7
    k_proj_mma<<<MTOT/32, 256>>>(nullptr, gb1, gw2, mask, 1, F0); // 8
    k_LL_mma<<<dim3(NN/64, BB*2), 256>>>(A);                    // 9
    k_finalmax<<<dim3(16, BB), 256>>>(gb2, mask);               // 10
    k_fc<<<1, 512>>>(fcw, fcb, out);                            // 11

    (void)in_sizes; (void)n_in; (void)out_size;
}

// round 16
// speedup vs baseline: 1.0885x; 1.0885x over previous
#include <cuda_runtime.h>
#include <math.h>
#include <float.h>
#include <stdint.h>

#define BB   8
#define NN   512
#define CC   256
#define HE   32
#define F0   64
#define OUTD 2
#define MTOT (BB*NN)   // 4096
#define PSTAGE 4

// ---------------- scratch ----------------
__device__ float g_xab[MTOT*64];
__device__ float g_Ap[BB*NN*NN];
__device__ float g_S0[MTOT];
__device__ float g_S1[MTOT];
__device__ float g_P0[MTOT*F0];
__device__ float g_P1[MTOT*F0];
__device__ float g_Y0[MTOT*F0];
__device__ float g_Y1[MTOT*F0];
__device__ int   g_gmax[BB*F0];

// ---------------- helpers ----------------
__device__ __forceinline__ float tf32_rn(float x) {
    uint32_t u;
    asm("cvt.rna.tf32.f32 %0, %1;" : "=r"(u) : "f"(x));
    return __uint_as_float(u);
}
__device__ __forceinline__ void mma_tf32(float c[4], const uint32_t a[4], const uint32_t b[2]) {
    asm volatile(
        "mma.sync.aligned.m16n8k8.row.col.f32.tf32.tf32.f32 "
        "{%0,%1,%2,%3}, {%4,%5,%6,%7}, {%8,%9}, {%0,%1,%2,%3};\n"
        : "+f"(c[0]), "+f"(c[1]), "+f"(c[2]), "+f"(c[3])
        : "r"(a[0]), "r"(a[1]), "r"(a[2]), "r"(a[3]), "r"(b[0]), "r"(b[1]));
}
__device__ __forceinline__ float dinv(float s) { return rsqrtf(s + 1.0f + 1e-5f); }
__device__ __forceinline__ float relu_(float x) { return fmaxf(x, 0.f); }
__device__ __forceinline__ uint32_t s2u(const void* p) {
    return (uint32_t)__cvta_generic_to_shared(p);
}
__device__ __forceinline__ void cpa16(uint32_t dst, const void* src) {
    asm volatile("cp.async.cg.shared.global [%0], [%1], 16;" :: "r"(dst), "l"(src) : "memory");
}
__device__ __forceinline__ void cpa_commit() {
    asm volatile("cp.async.commit_group;" ::: "memory");
}
__device__ __forceinline__ void cpa_wait2() {
    asm volatile("cp.async.wait_group 2;" ::: "memory");
}

// ---------------- colsum of A (direct) + zero S1/gmax ----------------
__global__ __launch_bounds__(256) void k_colsumA(const float* __restrict__ A) {
    int b = blockIdx.y, c0 = blockIdx.x*16;
    int tc = threadIdx.x & 15, tr = threadIdx.x >> 4;
    float s = 0.f;
    const float* base = A + (size_t)b*NN*NN;
#pragma unroll 8
    for (int r = tr; r < NN; r += 16)
        s += base[(size_t)r*NN + c0 + tc];
    __shared__ float sm[16][17];
    sm[tr][tc] = s;
    __syncthreads();
    if (tr == 0) {
        float tot = 0.f;
#pragma unroll
        for (int q = 0; q < 16; ++q) tot += sm[q][tc];
        g_S0[b*NN + c0 + tc] = tot;
    }
    int blk = blockIdx.y*32 + blockIdx.x;
    if (threadIdx.x < 16) g_S1[blk*16 + threadIdx.x] = 0.f;
    if (blk < 32 && threadIdx.x < 16) g_gmax[blk*16 + threadIdx.x] = 0;
}

// ---------------- g_xab = x @ [wa | wb], eb1 folded ----------------
__global__ __launch_bounds__(256) void k_xab(const float* __restrict__ x,
                                             const float* __restrict__ ew1,
                                             const float* __restrict__ eb1) {
    int m0 = blockIdx.x*64;
    __shared__ float As[16][64];
    __shared__ float Bs[16][64];
    int t = threadIdx.x;
    int tx = t & 15, ty = t >> 4;
    float acc[4][4] = {};

    for (int k0 = 0; k0 < CC; k0 += 16) {
        {
            int row = t >> 2, kq = (t & 3)*4;
            float4 v = *(const float4*)&x[(size_t)(m0+row)*CC + k0 + kq];
            As[kq+0][row] = v.x; As[kq+1][row] = v.y; As[kq+2][row] = v.z; As[kq+3][row] = v.w;
        }
        {
            int kk = t >> 4, nq = (t & 15)*4;
            const float* src = (nq < 32) ? &ew1[(size_t)(k0+kk)*HE + nq]
                                         : &ew1[(size_t)(k0+kk+CC)*HE + nq - 32];
            *(float4*)&Bs[kk][nq] = *(const float4*)src;
        }
        __syncthreads();
#pragma unroll
        for (int k = 0; k < 16; ++k) {
            float4 a = *(const float4*)&As[k][ty*4];
            float4 bv = *(const float4*)&Bs[k][tx*4];
            float av[4] = {a.x, a.y, a.z, a.w};
            float bb[4] = {bv.x, bv.y, bv.z, bv.w};
#pragma unroll
            for (int u = 0; u < 4; ++u)
#pragma unroll
                for (int v2 = 0; v2 < 4; ++v2)
                    acc[u][v2] = fmaf(av[u], bb[v2], acc[u][v2]);
        }
        __syncthreads();
    }
#pragma unroll
    for (int u = 0; u < 4; ++u) {
        int row = m0 + ty*4 + u;
        float o[4];
#pragma unroll
        for (int v2 = 0; v2 < 4; ++v2) {
            int col = tx*4 + v2;
            o[v2] = acc[u][v2] + (col >= 32 ? eb1[col-32] : 0.f);
        }
        *(float4*)&g_xab[(size_t)row*64 + tx*4] = make_float4(o[0], o[1], o[2], o[3]);
    }
}

// ---------------- fused edge-MLP + symmetrize + exp + mask + colsum(S1) ----------------
__global__ __launch_bounds__(256) void k_edge_sym(const float* __restrict__ mask,
                                                  const float* __restrict__ ew2,
                                                  const float* __restrict__ eb2) {
    int idx = blockIdx.x, bi = 0;
    while (idx >= 16 - bi) { idx -= 16 - bi; ++bi; }
    int bj = bi + idx;
    int b = blockIdx.y;
    int i0 = bi*32, j0 = bj*32;
    bool diag = (bi == bj);
    __shared__ float sin_[32][68];
    __shared__ float sjf[64][33];
    __shared__ __align__(16) float wv[32];
    __shared__ float mi_s[32], mj_s[32];
    __shared__ float red[8][32];
    int tx = threadIdx.x, ty = threadIdx.y;
    int t = ty*32 + tx;
    for (int q = t; q < 512; q += 256) {
        int node = q >> 4, c = (q & 15)*4;
        float4 vi = *(const float4*)&g_xab[(size_t)(b*NN + i0 + node)*64 + c];
        *(float4*)&sin_[node][c] = vi;
        float4 vj = *(const float4*)&g_xab[(size_t)(b*NN + j0 + node)*64 + c];
        sjf[c+0][node] = vj.x; sjf[c+1][node] = vj.y; sjf[c+2][node] = vj.z; sjf[c+3][node] = vj.w;
    }
    if (t < 32) { wv[t] = ew2[t]; mi_s[t] = mask[b*NN + i0 + t]; mj_s[t] = mask[b*NN + j0 + t]; }
    __syncthreads();

    float e2v = eb2[0];
    float acc1[4], acc2[4];
#pragma unroll
    for (int r = 0; r < 4; ++r) { acc1[r] = e2v; acc2[r] = e2v; }

#pragma unroll
    for (int kc = 0; kc < 32; kc += 4) {
        float4 wq = *(const float4*)&wv[kc];
        float aj0 = sjf[kc+0][tx], aj1 = sjf[kc+1][tx];
        float aj2 = sjf[kc+2][tx], aj3 = sjf[kc+3][tx];
        float bj0 = sjf[32+kc+0][tx], bj1 = sjf[32+kc+1][tx];
        float bj2 = sjf[32+kc+2][tx], bj3 = sjf[32+kc+3][tx];
#pragma unroll
        for (int r = 0; r < 4; ++r) {
            int il = ty + r*8;
            float4 ai = *(const float4*)&sin_[il][kc];
            float4 bi = *(const float4*)&sin_[il][32+kc];
            acc1[r] = fmaf(relu_(ai.x + bj0), wq.x, acc1[r]);
            acc1[r] = fmaf(relu_(ai.y + bj1), wq.y, acc1[r]);
            acc1[r] = fmaf(relu_(ai.z + bj2), wq.z, acc1[r]);
            acc1[r] = fmaf(relu_(ai.w + bj3), wq.w, acc1[r]);
            acc2[r] = fmaf(relu_(aj0 + bi.x), wq.x, acc2[r]);
            acc2[r] = fmaf(relu_(aj1 + bi.y), wq.y, acc2[r]);
            acc2[r] = fmaf(relu_(aj2 + bi.z), wq.z, acc2[r]);
            acc2[r] = fmaf(relu_(aj3 + bi.w), wq.w, acc2[r]);
        }
    }

    float colacc = 0.f;
#pragma unroll
    for (int r = 0; r < 4; ++r) {
        int il = ty + r*8, jl = tx;
        int gi = i0 + il, gj = j0 + jl;
        float v = 0.f;
        if (gi != gj && mi_s[il] > 0.f && mj_s[jl] > 0.f)
            v = __expf(0.5f*(acc1[r] + acc2[r]));
        g_Ap[((size_t)b*NN + gi)*NN + gj] = v;
        colacc += v;
        if (!diag) {
            g_Ap[((size_t)b*NN + gj)*NN + gi] = v;
            float rs = v;
#pragma unroll
            for (int off = 16; off; off >>= 1) rs += __shfl_xor_sync(0xffffffffu, rs, off);
            if (tx == 0) atomicAdd(&g_S1[b*NN + gi], rs);
        }
    }
    red[ty][tx] = colacc;
    __syncthreads();
    if (ty == 0) {
        float tot = 0.f;
#pragma unroll
        for (int q = 0; q < 8; ++q) tot += red[q][tx];
        atomicAdd(&g_S1[b*NN + j0 + tx], tot);
    }
}

// ---------------- projection v6: TF32 MMA, cp.async 4-stage, M=32 x N=128, BK=16 ----------------
__global__ __launch_bounds__(256) void k_proj_mma(const float* __restrict__ xin,
                                                  const float* __restrict__ biasPrev,
                                                  const float* __restrict__ W,
                                                  const float* __restrict__ mask,
                                                  int mode, int K) {
    int m0 = blockIdx.x*32;
    __shared__ float Araw[PSTAGE][32][20];
    __shared__ float Braw[PSTAGE][16][136];
    int t = threadIdx.x;
    int lane = t & 31, warp = t >> 5;
    int wm = warp >> 2, wn = warp & 3;
    int g = lane >> 2, tig = lane & 3;
    int s = wn >> 1;
    const float* Sp = s ? g_S1 : g_S0;
    float* P = s ? g_P1 : g_P0;

    float acc[4][4] = {};

    int arow = t >> 2, akq = (t & 3)*4;
    bool aload = (t < 128);
    int q0 = t*2, q1 = t*2 + 1;
    int bk0 = q0 >> 5, bn0 = (q0 & 31)*4;
    int bk1 = q1 >> 5, bn1 = (q1 & 31)*4;
    const float* WB0 = W + (size_t)(bn0 >= 64 ? K*F0 : 0);
    const float* WB1 = W + (size_t)(bn1 >= 64 ? K*F0 : 0);
    int bc0 = bn0 & 63, bc1 = bn1 & 63;

    int NCH = K >> 4;

    auto issue = [&](int c) {
        if (c < NCH) {
            int st = c & (PSTAGE-1);
            int k0 = c << 4;
            if (aload) {
                if (mode == 0) {
                    cpa16(s2u(&Araw[st][arow][akq]), &xin[(size_t)(m0+arow)*CC + k0 + akq]);
                } else {
                    int grow = m0 + arow;
                    float4 y0 = *(const float4*)&g_Y0[(size_t)grow*F0 + k0 + akq];
                    float4 y1 = *(const float4*)&g_Y1[(size_t)grow*F0 + k0 + akq];
                    float4 bp = *(const float4*)&biasPrev[k0 + akq];
                    float mk = mask[grow];
                    float4 v;
                    v.x = relu_((y0.x + y1.x + bp.x)*mk);
                    v.y = relu_((y0.y + y1.y + bp.y)*mk);
                    v.z = relu_((y0.z + y1.z + bp.z)*mk);
                    v.w = relu_((y0.w + y1.w + bp.w)*mk);
                    *(float4*)&Araw[st][arow][akq] = v;
                }
            }
            cpa16(s2u(&Braw[st][bk0][bn0]), &WB0[(size_t)(k0+bk0)*F0 + bc0]);
            cpa16(s2u(&Braw[st][bk1][bn1]), &WB1[(size_t)(k0+bk1)*F0 + bc1]);
        }
        cpa_commit();
    };

    issue(0); issue(1); issue(2);

    for (int c = 0; c < NCH; ++c) {
        cpa_wait2();
        __syncthreads();
        int st = c & (PSTAGE-1);
        int m = wm*16 + g;
#pragma unroll
        for (int kb = 0; kb < 16; kb += 8) {
            float r0 = Araw[st][m  ][kb+tig];
            float r1 = Araw[st][m+8][kb+tig];
            float r2 = Araw[st][m  ][kb+tig+4];
            float r3 = Araw[st][m+8][kb+tig+4];
            uint32_t ah[4], al[4], bh[4][2];
            float h0 = tf32_rn(r0), h1 = tf32_rn(r1), h2 = tf32_rn(r2), h3 = tf32_rn(r3);
            ah[0] = __float_as_uint(h0); al[0] = __float_as_uint(tf32_rn(r0 - h0));
            ah[1] = __float_as_uint(h1); al[1] = __float_as_uint(tf32_rn(r1 - h1));
            ah[2] = __float_as_uint(h2); al[2] = __float_as_uint(tf32_rn(r2 - h2));
            ah[3] = __float_as_uint(h3); al[3] = __float_as_uint(tf32_rn(r3 - h3));
#pragma unroll
            for (int nt = 0; nt < 4; ++nt) {
                int n = wn*32 + nt*8 + g;
                bh[nt][0] = __float_as_uint(tf32_rn(Braw[st][kb+tig  ][n]));
                bh[nt][1] = __float_as_uint(tf32_rn(Braw[st][kb+tig+4][n]));
            }
#pragma unroll
            for (int nt = 0; nt < 4; ++nt) {
                mma_tf32(acc[nt], al, bh[nt]);
                mma_tf32(acc[nt], ah, bh[nt]);
            }
        }
        __syncthreads();
        issue(c + 3);
    }

    int r0 = m0 + wm*16 + g;
    float d0 = dinv(Sp[r0]), d8 = dinv(Sp[r0+8]);
#pragma unroll
    for (int nt = 0; nt < 4; ++nt) {
        int cc = (wn*32 + nt*8 + 2*tig) & 63;
        *(float2*)&P[(size_t)r0*F0 + cc] =
            make_float2(tf32_rn(acc[nt][0]*d0), tf32_rn(acc[nt][1]*d0));
        *(float2*)&P[(size_t)(r0+8)*F0 + cc] =
            make_float2(tf32_rn(acc[nt][2]*d8), tf32_rn(acc[nt][3]*d8));
    }
}

// ---------------- Y_s = D_s*(A_s @ P_s + P_s) — TF32 MMA, cp.async 4-stage ----------------
// 64x64 tile, BK=16, 32 chunks, 8 warps 4(m) x 2(n). No split-K (pipeline hides latency).
__global__ __launch_bounds__(256) void k_LL_mma(const float* __restrict__ Ain) {
    int m0 = blockIdx.x*64;
    int z = blockIdx.y, b = z >> 1, s = z & 1;
    const float* Am = (s ? g_Ap : Ain) + (size_t)b*NN*NN;
    const float* P  = (s ? g_P1 : g_P0) + (size_t)b*NN*F0;
    float* Y        = (s ? g_Y1 : g_Y0) + (size_t)b*NN*F0;
    const float* Sp = (s ? g_S1 : g_S0) + b*NN;

    __shared__ float Araw[PSTAGE][64][20];   // [stage][m][k] stride 20 (bank-clean)
    __shared__ float Braw[PSTAGE][16][72];   // [stage][k][n] stride 72
    int t = threadIdx.x;
    int lane = t & 31, warp = t >> 5;
    int wm = warp >> 1, wn = warp & 1;
    int g = lane >> 2, tig = lane & 3;

    float acc[4][4] = {};

    // loaders: A 64x16 = 256 f4 (1/thread); B 16x64 = 256 f4 (1/thread)
    int arow = t >> 2, akq = (t & 3)*4;
    int bk = t >> 4, bnq = (t & 15)*4;

    const int NCH = NN >> 4;   // 32

    auto issue = [&](int c) {
        if (c < NCH) {
            int st = c & (PSTAGE-1);
            int k0 = c << 4;
            cpa16(s2u(&Araw[st][arow][akq]), &Am[(size_t)(m0+arow)*NN + k0 + akq]);
            cpa16(s2u(&Braw[st][bk][bnq]),   &P[(size_t)(k0+bk)*F0 + bnq]);
        }
        cpa_commit();
    };

    issue(0); issue(1); issue(2);

    for (int c = 0; c < NCH; ++c) {
        cpa_wait2();
        __syncthreads();
        int st = c & (PSTAGE-1);
        int m = wm*16 + g;
#pragma unroll
        for (int kb = 0; kb < 16; kb += 8) {
            uint32_t af[4], bf[4][2];
            af[0] = __float_as_uint(tf32_rn(Araw[st][m  ][kb+tig]));
            af[1] = __float_as_uint(tf32_rn(Araw[st][m+8][kb+tig]));
            af[2] = __float_as_uint(tf32_rn(Araw[st][m  ][kb+tig+4]));
            af[3] = __float_as_uint(tf32_rn(Araw[st][m+8][kb+tig+4]));
#pragma unroll
            for (int nt = 0; nt < 4; ++nt) {
                int n = wn*32 + nt*8 + g;
                bf[nt][0] = __float_as_uint(tf32_rn(Braw[st][kb+tig  ][n]));
                bf[nt][1] = __float_as_uint(tf32_rn(Braw[st][kb+tig+4][n]));
            }
#pragma unroll
            for (int nt = 0; nt < 4; ++nt)
                mma_tf32(acc[nt], af, bf[nt]);
        }
        __syncthreads();
        issue(c + 3);
    }

    int r0 = m0 + wm*16 + g;
    float d0 = dinv(Sp[r0]), d8 = dinv(Sp[r0+8]);
#pragma unroll
    for (int nt = 0; nt < 4; ++nt) {
        int cc = wn*32 + nt*8 + 2*tig;
        float2 p0 = *(const float2*)&P[(size_t)r0*F0 + cc];
        float2 p8 = *(const float2*)&P[(size_t)(r0+8)*F0 + cc];
        *(float2*)&Y[(size_t)r0*F0 + cc]     = make_float2(d0*(acc[nt][0] + p0.x), d0*(acc[nt][1] + p0.y));
        *(float2*)&Y[(size_t)(r0+8)*F0 + cc] = make_float2(d8*(acc[nt][2] + p8.x), d8*(acc[nt][3] + p8.y));
    }
}

// ---------------- final stage 1 ----------------
__global__ __launch_bounds__(256) void k_finalmax(const float* __restrict__ gb2,
                                                  const float* __restrict__ mask) {
    int b = blockIdx.y, r0 = blockIdx.x*32;
    int f = threadIdx.x & 63;
    int ty = threadIdx.x >> 6;
    float bf = gb2[f];
    float m = 0.f;
#pragma unroll
    for (int r = 0; r < 8; ++r) {
        int row = b*NN + r0 + ty + r*4;
        float h = (g_Y0[(size_t)row*F0 + f] + g_Y1[(size_t)row*F0 + f] + bf)*mask[row];
        m = fmaxf(m, h);
    }
    __shared__ float red[4][64];
    red[ty][f] = m;
    __syncthreads();
    if (ty == 0) {
        float mm = fmaxf(fmaxf(red[0][f], red[1][f]), fmaxf(red[2][f], red[3][f]));
        atomicMax(&g_gmax[b*F0 + f], __float_as_int(mm));
    }
}

// ---------------- final stage 2 ----------------
__global__ __launch_bounds__(512) void k_fc(const float* __restrict__ fcw,
                                            const float* __restrict__ fcb,
                                            float* __restrict__ out) {
    __shared__ float gs[BB][F0];
    int t = threadIdx.x;
    gs[t >> 6][t & 63] = __int_as_float(g_gmax[t]);
    __syncthreads();
    if (t < BB*OUTD) {
        int b = t >> 1, o = t & 1;
        float acc = fcb[o];
#pragma unroll
        for (int q = 0; q < F0; ++q) acc = fmaf(gs[b][q], fcw[q*OUTD + o], acc);
        out[b*OUTD + o] = acc;
    }
}

// ---------------- launch ----------------
extern "C" void kernel_launch(void* const* d_in, const int* in_sizes, int n_in,
                              void* d_out, int out_size) {
    const float* x    = (const float*)d_in[0];
    const float* A    = (const float*)d_in[1];
    const float* mask = (const float*)d_in[2];
    const float* ew1  = (const float*)d_in[3];
    const float* eb1  = (const float*)d_in[4];
    const float* ew2  = (const float*)d_in[5];
    const float* eb2  = (const float*)d_in[6];
    const float* gw0  = (const float*)d_in[7];
    const float* gb0  = (const float*)d_in[8];
    const float* gw1  = (const float*)d_in[9];
    const float* gb1  = (const float*)d_in[10];
    const float* gw2  = (const float*)d_in[11];
    const float* gb2  = (const float*)d_in[12];
    const float* fcw  = (const float*)d_in[13];
    const float* fcb  = (const float*)d_in[14];
    float* out = (float*)d_out;

    k_colsumA<<<dim3(32, BB), 256>>>(A);                        // 1 (zeros S1, gmax)
    k_xab<<<MTOT/64, 256>>>(x, ew1, eb1);                       // 2
    k_edge_sym<<<dim3(136, BB), dim3(32, 8)>>>(mask, ew2, eb2); // 3
    k_proj_mma<<<MTOT/32, 256>>>(x, nullptr, gw0, mask, 0, CC); // 4 (profiled slot)
    k_LL_mma<<<dim3(NN/64, BB*2), 256>>>(A);                    // 5
    k_proj_mma<<<MTOT/32, 256>>>(nullptr, gb0, gw1, mask, 1, F0); // 6
    k_LL_mma<<<dim3(NN/64, BB*2), 256>>>(A);                    // 7
    k_proj_mma<<<MTOT/32, 256>>>(nullptr, gb1, gw2, mask, 1, F0); // 8
    k_LL_mma<<<dim3(NN/64, BB*2), 256>>>(A);                    // 9
    k_finalmax<<<dim3(16, BB), 256>>>(gb2, mask);               // 10
    k_fc<<<1, 512>>>(fcw, fcb, out);                            // 11

    (void)in_sizes; (void)n_in; (void)out_size;
}